// round 2
// baseline (speedup 1.0000x reference)
#include <cuda_runtime.h>
#include <math.h>

#define N_PTS 16384            // 2*8192 points per cloud
#define TILE 1024              // float4 targets per smem tile
#define NTILES (N_PTS / TILE)  // 16
#define THREADS 128
#define WARPS (THREADS / 32)   // 4
#define SRC_PER_WARP 4
#define SRC_PER_BLOCK (WARPS * SRC_PER_WARP)   // 16
#define NBLOCKS (N_PTS / SRC_PER_BLOCK)        // 1024
#define KNN 5

// Scratch (no allocation allowed anywhere)
__device__ float4 g_tgt[N_PTS];
__device__ float  g_bsum[NBLOCKS];
__device__ int    g_bcnt[NBLOCKS];

// ---------------------------------------------------------------------------
// Prep: targets -> (-2x, -2y, -2z, |t|^2); invalid (all-zero) -> w = 1e20
// so d = sqrt(1e20) = 1e10 (matches reference BIG).
// ---------------------------------------------------------------------------
__global__ void prep_kernel(const float* __restrict__ tgt) {
    int i = blockIdx.x * blockDim.x + threadIdx.x;
    if (i < N_PTS) {
        float x = tgt[3 * i + 0];
        float y = tgt[3 * i + 1];
        float z = tgt[3 * i + 2];
        bool valid = (x != 0.0f) || (y != 0.0f) || (z != 0.0f);
        float t2 = fmaf(x, x, fmaf(y, y, z * z));
        float4 v;
        if (valid) { v.x = -2.0f * x; v.y = -2.0f * y; v.z = -2.0f * z; v.w = t2; }
        else       { v.x = 0.0f;      v.y = 0.0f;      v.z = 0.0f;      v.w = 1e20f; }
        g_tgt[i] = v;
    }
}

// Branchless sorted insert into ascending m0..m4.
// Safe to call unconditionally: if q >= m4 it is an exact no-op.
__device__ __forceinline__ void insert5(float q, float& m0, float& m1,
                                        float& m2, float& m3, float& m4) {
    float t0 = fminf(m0, q);
    float t1 = fminf(m1, fmaxf(m0, q));
    float t2 = fminf(m2, fmaxf(m1, q));
    float t3 = fminf(m3, fmaxf(m2, q));
    float t4 = fminf(m4, fmaxf(m3, q));
    m0 = t0; m1 = t1; m2 = t2; m3 = t3; m4 = t4;
}

// ---------------------------------------------------------------------------
// Main: warp owns 4 sources; 32 lanes sweep 32 different targets per step.
// q = |t|^2 - 2 s.t  (order-equivalent to d^2; s^2 added at the end).
// Top-5 lists are replicated across all lanes and updated warp-uniformly
// via ballot + shfl + branchless insert network -> no divergence.
// ---------------------------------------------------------------------------
__global__ __launch_bounds__(THREADS)
void knn_main(const float* __restrict__ src) {
    __shared__ float4 s_tile[2][TILE];      // 32 KB double buffer
    __shared__ float  red_s[WARPS];
    __shared__ int    red_c[WARPS];

    const int tid  = threadIdx.x;
    const int lane = tid & 31;
    const int warp = tid >> 5;

    const int sbase = blockIdx.x * SRC_PER_BLOCK + warp * SRC_PER_WARP;
    float sx[SRC_PER_WARP], sy[SRC_PER_WARP], sz[SRC_PER_WARP];
#pragma unroll
    for (int s = 0; s < SRC_PER_WARP; ++s) {
        sx[s] = src[3 * (sbase + s) + 0];
        sy[s] = src[3 * (sbase + s) + 1];
        sz[s] = src[3 * (sbase + s) + 2];
    }

    float m[SRC_PER_WARP][KNN];
#pragma unroll
    for (int s = 0; s < SRC_PER_WARP; ++s)
#pragma unroll
        for (int k = 0; k < KNN; ++k) m[s][k] = 1e30f;

    // prefetch tile 0 into registers, then smem
    const int PER_THREAD = TILE / THREADS;   // 8 float4 per thread
    float4 stg[PER_THREAD];
#pragma unroll
    for (int i = 0; i < PER_THREAD; ++i) stg[i] = g_tgt[i * THREADS + tid];
#pragma unroll
    for (int i = 0; i < PER_THREAD; ++i) s_tile[0][i * THREADS + tid] = stg[i];

    int buf = 0;
    for (int tile = 0; tile < NTILES; ++tile) {
        __syncthreads();   // current buf fully stored; prev processing done
        if (tile + 1 < NTILES) {
#pragma unroll
            for (int i = 0; i < PER_THREAD; ++i)
                stg[i] = g_tgt[(tile + 1) * TILE + i * THREADS + tid];
        }

        const float4* T = s_tile[buf];
#pragma unroll 4
        for (int step = 0; step < TILE / 32; ++step) {
            float4 v = T[step * 32 + lane];
#pragma unroll
            for (int s = 0; s < SRC_PER_WARP; ++s) {
                float q = fmaf(sx[s], v.x, fmaf(sy[s], v.y, fmaf(sz[s], v.z, v.w)));
                unsigned bal = __ballot_sync(0xffffffffu, q < m[s][4]);
                if (bal) {
                    do {
                        int ln = __ffs(bal) - 1;
                        bal &= bal - 1;
                        float qq = __shfl_sync(0xffffffffu, q, ln);
                        insert5(qq, m[s][0], m[s][1], m[s][2], m[s][3], m[s][4]);
                    } while (bal);
                }
            }
        }

        if (tile + 1 < NTILES) {
#pragma unroll
            for (int i = 0; i < PER_THREAD; ++i)
                s_tile[buf ^ 1][i * THREADS + tid] = stg[i];
        }
        buf ^= 1;
    }

    // finalize this warp's sources (all lanes hold identical lists)
    float wsum = 0.0f;
    int   wcnt = 0;
#pragma unroll
    for (int s = 0; s < SRC_PER_WARP; ++s) {
        float s2 = fmaf(sx[s], sx[s], fmaf(sy[s], sy[s], sz[s] * sz[s]));
        bool valid = (sx[s] != 0.0f) || (sy[s] != 0.0f) || (sz[s] != 0.0f);
        float acc = 0.0f;
#pragma unroll
        for (int k = 0; k < KNN; ++k)
            acc += sqrtf(fmaxf(m[s][k] + s2, 1e-12f));
        if (valid) { wsum += acc; wcnt += 1; }
    }

    if (lane == 0) { red_s[warp] = wsum; red_c[warp] = wcnt; }
    __syncthreads();
    if (tid == 0) {
        float bs = 0.0f; int bc = 0;
#pragma unroll
        for (int w = 0; w < WARPS; ++w) { bs += red_s[w]; bc += red_c[w]; }
        g_bsum[blockIdx.x] = bs;
        g_bcnt[blockIdx.x] = bc;
    }
}

// ---------------------------------------------------------------------------
// Finalize: reduce 1024 per-block partials in double, divide, write scalar.
// ---------------------------------------------------------------------------
__global__ void finalize_kernel(float* __restrict__ out) {
    __shared__ double ds[256];
    __shared__ int    di[256];
    int tid = threadIdx.x;
    double s = 0.0; int c = 0;
    for (int i = tid; i < NBLOCKS; i += 256) { s += (double)g_bsum[i]; c += g_bcnt[i]; }
    ds[tid] = s; di[tid] = c;
    __syncthreads();
#pragma unroll
    for (int off = 128; off > 0; off >>= 1) {
        if (tid < off) { ds[tid] += ds[tid + off]; di[tid] += di[tid + off]; }
        __syncthreads();
    }
    if (tid == 0) out[0] = (float)(ds[0] / ((double)di[0] * KNN));
}

// ---------------------------------------------------------------------------
extern "C" void kernel_launch(void* const* d_in, const int* in_sizes, int n_in,
                              void* d_out, int out_size) {
    const float* src = (const float*)d_in[0];  // source_pc (2,8192,3)
    const float* tgt = (const float*)d_in[1];  // target_pc (2,8192,3)
    float* out = (float*)d_out;

    prep_kernel<<<N_PTS / 256, 256>>>(tgt);
    knn_main<<<NBLOCKS, THREADS>>>(src);
    finalize_kernel<<<1, 256>>>(out);
}

// round 3
// speedup vs baseline: 1.5732x; 1.5732x over previous
#include <cuda_runtime.h>
#include <math.h>

#define N_PTS 16384            // 2*8192 points, both batches flattened
#define KNN 5
#define NB 256                 // x-slab buckets
#define XMIN (-5.0f)
#define BWIDTH (10.0f / NB)    // 0.0390625
#define INV_BW (NB / 10.0f)

#define MAIN_THREADS 256
#define MAIN_WARPS (MAIN_THREADS / 32)          // 8
#define SRC_PER_WARP 4
#define SRC_PER_BLOCK (MAIN_WARPS * SRC_PER_WARP)   // 32
#define MAIN_BLOCKS (N_PTS / SRC_PER_BLOCK)         // 512

// ---- scratch (no allocation allowed anywhere) ----
__device__ float4 g_tsort[N_PTS];   // (-2x,-2y,-2z,t^2) bucket-ordered; invalid w=1e20
__device__ float4 g_ssort[N_PTS];   // (x,y,z, valid? s2 : -1) bucket-ordered
__device__ int    g_thist[NB], g_shist[NB];
__device__ int    g_tstart[NB + 1], g_sstart[NB + 1];
__device__ int    g_tcur[NB], g_scur[NB];
__device__ float  g_bsum[MAIN_BLOCKS];
__device__ int    g_bcnt[MAIN_BLOCKS];

__device__ __forceinline__ int bucket_of(float x) {
    int b = (int)floorf((x - XMIN) * INV_BW);
    return min(NB - 1, max(0, b));
}

// ---------------------------------------------------------------------------
__global__ void zero_kernel() {
    int t = threadIdx.x;
    if (t < NB) { g_thist[t] = 0; g_shist[t] = 0; }
}

// histogram of x over buckets for targets (gid < N_PTS) and sources
__global__ void hist_kernel(const float* __restrict__ src,
                            const float* __restrict__ tgt) {
    __shared__ int sh[2 * NB];
    for (int i = threadIdx.x; i < 2 * NB; i += blockDim.x) sh[i] = 0;
    __syncthreads();
    int gid = blockIdx.x * blockDim.x + threadIdx.x;     // 0..32767
    if (gid < N_PTS) {
        atomicAdd(&sh[bucket_of(tgt[3 * gid])], 1);
    } else {
        atomicAdd(&sh[NB + bucket_of(src[3 * (gid - N_PTS)])], 1);
    }
    __syncthreads();
    for (int i = threadIdx.x; i < NB; i += blockDim.x) {
        if (sh[i])      atomicAdd(&g_thist[i], sh[i]);
        if (sh[NB + i]) atomicAdd(&g_shist[i], sh[NB + i]);
    }
}

// exclusive scan of both histograms (1 block, NB threads)
__global__ void scan_kernel() {
    __shared__ int t[NB], s[NB];
    int b = threadIdx.x;
    t[b] = g_thist[b]; s[b] = g_shist[b];
    __syncthreads();
#pragma unroll
    for (int off = 1; off < NB; off <<= 1) {
        int ta = (b >= off) ? t[b - off] : 0;
        int sa = (b >= off) ? s[b - off] : 0;
        __syncthreads();
        t[b] += ta; s[b] += sa;
        __syncthreads();
    }
    int ts = t[b] - g_thist[b];   // exclusive
    int ss = s[b] - g_shist[b];
    g_tstart[b] = ts;  g_tcur[b] = ts;
    g_sstart[b] = ss;  g_scur[b] = ss;
    if (b == NB - 1) { g_tstart[NB] = N_PTS; g_sstart[NB] = N_PTS; }
}

// scatter into bucket order, transforming on the way
__global__ void scatter_kernel(const float* __restrict__ src,
                               const float* __restrict__ tgt) {
    int gid = blockIdx.x * blockDim.x + threadIdx.x;
    if (gid < N_PTS) {
        float x = tgt[3 * gid], y = tgt[3 * gid + 1], z = tgt[3 * gid + 2];
        bool valid = (x != 0.0f) || (y != 0.0f) || (z != 0.0f);
        float t2 = fmaf(x, x, fmaf(y, y, z * z));
        float4 v;
        if (valid) { v.x = -2.0f * x; v.y = -2.0f * y; v.z = -2.0f * z; v.w = t2; }
        else       { v.x = 0.0f;      v.y = 0.0f;      v.z = 0.0f;      v.w = 1e30f; }
        int pos = atomicAdd(&g_tcur[bucket_of(x)], 1);
        g_tsort[pos] = v;
    } else {
        int i = gid - N_PTS;
        float x = src[3 * i], y = src[3 * i + 1], z = src[3 * i + 2];
        bool valid = (x != 0.0f) || (y != 0.0f) || (z != 0.0f);
        float s2 = fmaf(x, x, fmaf(y, y, z * z));
        float4 v; v.x = x; v.y = y; v.z = z; v.w = valid ? s2 : -1.0f;
        int pos = atomicAdd(&g_scur[bucket_of(x)], 1);
        g_ssort[pos] = v;
    }
}

// branchless sorted insert, ascending m0..m4 (exact no-op when q >= m4)
__device__ __forceinline__ void insert5(float q, float& m0, float& m1,
                                        float& m2, float& m3, float& m4) {
    float t0 = fminf(m0, q);
    float t1 = fminf(m1, fmaxf(m0, q));
    float t2 = fminf(m2, fmaxf(m1, q));
    float t3 = fminf(m3, fmaxf(m2, q));
    float t4 = fminf(m4, fmaxf(m3, q));
    m0 = t0; m1 = t1; m2 = t2; m3 = t3; m4 = t4;
}

// ---------------------------------------------------------------------------
// Main: each warp owns 4 bucket-adjacent sources; scans target buckets
// outward from its own slab with an exact x lower-bound cutoff.
// Top-5 lists (q-space) replicated across lanes; updates via ballot+shfl.
// ---------------------------------------------------------------------------
__global__ __launch_bounds__(MAIN_THREADS)
void knn_main() {
    __shared__ float red_s[MAIN_WARPS];
    __shared__ int   red_c[MAIN_WARPS];

    const int lane = threadIdx.x & 31;
    const int warp = threadIdx.x >> 5;
    const int sbase = (blockIdx.x * MAIN_WARPS + warp) * SRC_PER_WARP;

    float sx[SRC_PER_WARP], sy[SRC_PER_WARP], sz[SRC_PER_WARP], s2v[SRC_PER_WARP];
    bool  sval[SRC_PER_WARP];
    float xlo = 1e30f, xhi = -1e30f;
#pragma unroll
    for (int s = 0; s < SRC_PER_WARP; ++s) {
        float4 v = g_ssort[sbase + s];
        sx[s] = v.x; sy[s] = v.y; sz[s] = v.z;
        sval[s] = (v.w >= 0.0f);
        s2v[s]  = fmaxf(v.w, 0.0f);
        if (sval[s]) { xlo = fminf(xlo, v.x); xhi = fmaxf(xhi, v.x); }
    }

    float m[SRC_PER_WARP][KNN];
#pragma unroll
    for (int s = 0; s < SRC_PER_WARP; ++s)
#pragma unroll
        for (int k = 0; k < KNN; ++k) m[s][k] = 1e20f;

    if (xlo <= xhi) {   // at least one valid source
        const int b0 = bucket_of(xlo);
        const int b1 = bucket_of(xhi);
        int up = b0;          // next bucket upward  (starts at home slab)
        int dn = b0 - 1;      // next bucket downward

        // processes bucket b; returns nothing, updates m[][]
        auto process_bucket = [&](int b) {
            int st = g_tstart[b];
            int en = g_tstart[b + 1];
            if (st >= en) return;
            int i = st + lane;
            float4 v;
            if (i < en) v = g_tsort[i];
            else { v.x = 0.0f; v.y = 0.0f; v.z = 0.0f; v.w = 1e30f; }
            for (int i0 = st; i0 < en; i0 += 32) {
                // prefetch next step
                float4 vn;
                int in = i0 + 32 + lane;
                if (in < en) vn = g_tsort[in];
                else { vn.x = 0.0f; vn.y = 0.0f; vn.z = 0.0f; vn.w = 1e30f; }
#pragma unroll
                for (int s = 0; s < SRC_PER_WARP; ++s) {
                    float q = fmaf(sx[s], v.x,
                              fmaf(sy[s], v.y,
                              fmaf(sz[s], v.z, v.w)));
                    unsigned bal = __ballot_sync(0xffffffffu, q < m[s][4]);
                    while (bal) {
                        int ln = __ffs(bal) - 1;
                        bal &= bal - 1;
                        float qq = __shfl_sync(0xffffffffu, q, ln);
                        insert5(qq, m[s][0], m[s][1], m[s][2], m[s][3], m[s][4]);
                    }
                }
                v = vn;
            }
        };

        // home slab(s) first (x lower bound 0)
        for (int b = b0; b <= b1; ++b) process_bucket(b);
        up = b1 + 1;

        while (true) {
            // warp-uniform squared-distance bound (d^2 = q + s^2)
            float r2max = -1e30f;
#pragma unroll
            for (int s = 0; s < SRC_PER_WARP; ++s)
                if (sval[s]) r2max = fmaxf(r2max, m[s][4] + s2v[s]);

            float dup = (up < NB) ? fmaxf(XMIN + up * BWIDTH - xhi, 0.0f) : 1e30f;
            float ddn = (dn >= 0) ? fmaxf(xlo - (XMIN + (dn + 1) * BWIDTH), 0.0f) : 1e30f;
            float dmin = fminf(dup, ddn);
            if (dmin * dmin > r2max) break;
            if (dup <= ddn) { process_bucket(up); ++up; }
            else            { process_bucket(dn); --dn; }
        }
    }

    // finalize this warp's sources (lists identical on all lanes)
    float wsum = 0.0f; int wcnt = 0;
#pragma unroll
    for (int s = 0; s < SRC_PER_WARP; ++s) {
        float acc = 0.0f;
#pragma unroll
        for (int k = 0; k < KNN; ++k)
            acc += sqrtf(fmaxf(m[s][k] + s2v[s], 1e-12f));
        if (sval[s]) { wsum += acc; wcnt += 1; }
    }

    if (lane == 0) { red_s[warp] = wsum; red_c[warp] = wcnt; }
    __syncthreads();
    if (threadIdx.x == 0) {
        float bs = 0.0f; int bc = 0;
#pragma unroll
        for (int w = 0; w < MAIN_WARPS; ++w) { bs += red_s[w]; bc += red_c[w]; }
        g_bsum[blockIdx.x] = bs;
        g_bcnt[blockIdx.x] = bc;
    }
}

// ---------------------------------------------------------------------------
__global__ void finalize_kernel(float* __restrict__ out) {
    __shared__ double ds[256];
    __shared__ int    di[256];
    int tid = threadIdx.x;
    double s = 0.0; int c = 0;
    for (int i = tid; i < MAIN_BLOCKS; i += 256) { s += (double)g_bsum[i]; c += g_bcnt[i]; }
    ds[tid] = s; di[tid] = c;
    __syncthreads();
#pragma unroll
    for (int off = 128; off > 0; off >>= 1) {
        if (tid < off) { ds[tid] += ds[tid + off]; di[tid] += di[tid + off]; }
        __syncthreads();
    }
    if (tid == 0) out[0] = (float)(ds[0] / ((double)di[0] * KNN));
}

// ---------------------------------------------------------------------------
extern "C" void kernel_launch(void* const* d_in, const int* in_sizes, int n_in,
                              void* d_out, int out_size) {
    const float* src = (const float*)d_in[0];  // source_pc (2,8192,3)
    const float* tgt = (const float*)d_in[1];  // target_pc (2,8192,3)
    float* out = (float*)d_out;

    zero_kernel<<<1, 256>>>();
    hist_kernel<<<2 * N_PTS / 256, 256>>>(src, tgt);
    scan_kernel<<<1, NB>>>();
    scatter_kernel<<<2 * N_PTS / 256, 256>>>(src, tgt);
    knn_main<<<MAIN_BLOCKS, MAIN_THREADS>>>();
    finalize_kernel<<<1, 256>>>(out);
}